// round 14
// baseline (speedup 1.0000x reference)
#include <cuda_runtime.h>

// Problem constants: N_UNIQUE=10000, N_BASES=10, FILTERS=16, B=32, L=100000
#define N_UNIQUE 10000
#define N_BASES  10
#define FILTERS  16
#define N_ELEMS  (32 * 100000)           // 3,200,000
#define N_OUT4   (N_ELEMS * 4)           // 12,800,000 float4 outputs
#define UNROLL   4
#define TPB      256
#define CHUNK    (TPB * UNROLL)          // 1024 float4 per chunk
#define N_CHUNKS (N_OUT4 / CHUNK)        // 12500 exactly
#define GATHER_BLOCKS (148 * 8)          // one full wave at 8 CTAs/SM

// Precomputed bias-fused unique-value table, fp32 (device global scratch).
__device__ float4 g_shrunk4[N_UNIQUE * 4];   // [n_unique][16 floats] as 4x float4

// Kernel 1: shrunk_biased[u][f] = sum_b X_spline[u][b]*kernel[b][f] + bias[f]
__global__ void precompute_shrunk(const float* __restrict__ X_spline,
                                  const float* __restrict__ kern,
                                  const float* __restrict__ bias) {
    int t = blockIdx.x * blockDim.x + threadIdx.x;
    if (t >= N_UNIQUE * FILTERS) return;
    int u = t >> 4;
    int f = t & 15;
    float acc = __ldg(bias + f);
#pragma unroll
    for (int b = 0; b < N_BASES; ++b)
        acc = fmaf(__ldg(X_spline + u * N_BASES + b), __ldg(kern + b * FILTERS + f), acc);
    reinterpret_cast<float*>(g_shrunk4)[t] = acc;
}

// Kernel 2: out[e][f] = table[idx[e]][f].
// PERSISTENT single-wave grid: 1184 blocks (8/SM), each grid-strides over the
// 12500 chunks — no wave transitions, no ragged tail, warm L1 per SM.
// Per chunk a thread owns 4 float4 slots: slot i -> element e=i>>2, quarter
// j=i&3; all loads/stores fully coalesced (proven R2 pattern).
__global__ __launch_bounds__(TPB, 8) void gather_out(const int* __restrict__ idx,
                                                     float4* __restrict__ out4) {
    for (unsigned c = blockIdx.x; c < N_CHUNKS; c += GATHER_BLOCKS) {
        const unsigned base = c * CHUNK + threadIdx.x;

        // Phase 1: 4 independent idx loads (streamed — read exactly once).
        int u[UNROLL];
#pragma unroll
        for (int k = 0; k < UNROLL; ++k)
            u[k] = __ldcs(idx + ((base + k * TPB) >> 2));

        // Phase 2: 4 independent table gathers (L2-resident).
        float4 v[UNROLL];
#pragma unroll
        for (int k = 0; k < UNROLL; ++k) {
            unsigned i = base + k * TPB;
            v[k] = __ldg(&g_shrunk4[(unsigned)u[k] * 4u + (i & 3u)]);
        }

        // Phase 3: 4 streaming stores (write-once, evict-first).
#pragma unroll
        for (int k = 0; k < UNROLL; ++k)
            __stcs(out4 + (base + k * TPB), v[k]);
    }
}

extern "C" void kernel_launch(void* const* d_in, const int* in_sizes, int n_in,
                              void* d_out, int out_size) {
    // Identify inputs by element count (all distinct):
    // idx: 3,200,000 | X_spline: 100,000 | kernel: 160 | bias: 16
    const int*   idx      = nullptr;
    const float* X_spline = nullptr;
    const float* kern     = nullptr;
    const float* bias     = nullptr;
    for (int i = 0; i < n_in; ++i) {
        switch (in_sizes[i]) {
            case N_ELEMS:             idx      = (const int*)  d_in[i]; break;
            case N_UNIQUE * N_BASES:  X_spline = (const float*)d_in[i]; break;
            case N_BASES * FILTERS:   kern     = (const float*)d_in[i]; break;
            case FILTERS:             bias     = (const float*)d_in[i]; break;
            default: break;
        }
    }

    {
        int total = N_UNIQUE * FILTERS;
        precompute_shrunk<<<(total + TPB - 1) / TPB, TPB>>>(X_spline, kern, bias);
    }
    gather_out<<<GATHER_BLOCKS, TPB>>>(idx, (float4*)d_out);
}